// round 15
// baseline (speedup 1.0000x reference)
#include <cuda_runtime.h>
#include <cuda_bf16.h>
#include <math.h>
#include <stdint.h>

#define B_    8
#define L_    2048
#define D_    512
#define Y_    8921
#define YPAD_ 8960                 // 35 * 256
#define ROWS_ (B_ * Y_)            // 71368

// ---- static device scratch (no runtime allocation allowed) ----
__device__ float g_partials[Y_];
__device__ __align__(16) __nv_bfloat16 g_U_hi[YPAD_ * D_];
__device__ __align__(16) __nv_bfloat16 g_U_lo[YPAD_ * D_];
__device__ __align__(16) __nv_bfloat16 g_x_hi[B_ * L_ * D_];                  // [b][l][d]
__device__ __align__(16) __nv_bfloat16 g_x_lo[B_ * L_ * D_];
__device__ __align__(16) __nv_bfloat16 g_xT_hi[B_ * D_ * L_];                 // [b][d][l]
__device__ __align__(16) __nv_bfloat16 g_xT_lo[B_ * D_ * L_];
__device__ __align__(16) __nv_bfloat16 g_alpha_hi[(size_t)B_ * YPAD_ * L_];
__device__ __align__(16) __nv_bfloat16 g_alpha_lo[(size_t)B_ * YPAD_ * L_];

// ---- helpers ----
__device__ __forceinline__ uint32_t smem_u32(const void* p) {
    uint32_t a;
    asm("{ .reg .u64 t; cvta.to.shared.u64 t, %1; cvt.u32.u64 %0, t; }" : "=r"(a) : "l"(p));
    return a;
}
__device__ __forceinline__ void ldsm4(uint32_t addr, uint32_t* r) {
    asm volatile("ldmatrix.sync.aligned.m8n8.x4.shared.b16 {%0,%1,%2,%3}, [%4];"
        : "=r"(r[0]), "=r"(r[1]), "=r"(r[2]), "=r"(r[3]) : "r"(addr));
}
__device__ __forceinline__ void mma16816(float* c, const uint32_t* a, const uint32_t* b) {
    asm volatile("mma.sync.aligned.m16n8k16.row.col.f32.bf16.bf16.f32 "
        "{%0,%1,%2,%3}, {%4,%5,%6,%7}, {%8,%9}, {%0,%1,%2,%3};"
        : "+f"(c[0]), "+f"(c[1]), "+f"(c[2]), "+f"(c[3])
        : "r"(a[0]), "r"(a[1]), "r"(a[2]), "r"(a[3]), "r"(b[0]), "r"(b[1]));
}

// SMEM tile geometry: rows x 32 bf16 (64B data) with 80B pitch.
// 80 = 5*16: rows 16B-aligned (ldmatrix-legal); 8-row phases hit banks
// (20r mod 32) = full partition -> conflict-free ldmatrix by construction.
#define PITCH_B    80
#define A_TILE_SB  (256 * PITCH_B)    // 20480 (M-tile 256)
#define B_TILE_SB  (128 * PITCH_B)    // 10240 (N-tile 128)
#define STAGE_SB   (2 * A_TILE_SB + 2 * B_TILE_SB)   // 61440
#define SMEM_GEMM  (2 * STAGE_SB)                    // 122880, double-buffered
// stage offsets
#define OFF_AH 0
#define OFF_AL A_TILE_SB
#define OFF_BH (2 * A_TILE_SB)
#define OFF_BL (2 * A_TILE_SB + B_TILE_SB)

// cp.async a 256(rows) x 32(k) bf16 tile (512 threads, 2 iters).
__device__ __forceinline__ void cp_tileA(uint32_t dst, const __nv_bfloat16* __restrict__ src,
                                         int kb, int ldk, int tid)
{
#pragma unroll
    for (int i = 0; i < 2; i++) {
        int seg = tid + i * 512;            // 0..1023 segments of 16B
        int row = seg >> 2;                 // 4 segments per row
        int u   = seg & 3;
        const void* g = src + (size_t)row * ldk + kb + u * 8;
        uint32_t d = dst + (uint32_t)row * PITCH_B + (uint32_t)(u << 4);
        asm volatile("cp.async.ca.shared.global [%0], [%1], 16;" :: "r"(d), "l"(g));
    }
}
// cp.async a 128(rows) x 32(k) bf16 tile (512 threads, 1 iter).
__device__ __forceinline__ void cp_tileB(uint32_t dst, const __nv_bfloat16* __restrict__ src,
                                         int kb, int ldk, int tid)
{
    int row = tid >> 2;
    int u   = tid & 3;
    const void* g = src + (size_t)row * ldk + kb + u * 8;
    uint32_t d = dst + (uint32_t)row * PITCH_B + (uint32_t)(u << 4);
    asm volatile("cp.async.ca.shared.global [%0], [%1], 16;" :: "r"(d), "l"(g));
}

// ---------------------------------------------------------------------------
// HMMA GEMM body: C[m][n] = sum_k A[m][k] * B[n][k], CTA tile 256x128.
// A,B pre-split bf16 hi/lo, K-contiguous. fp32 accumulate, 3-product split.
// 16 warps (4m x 4n), warp tile m64 x n32. K-chunk 32, cp.async 2-stage
// pipeline, ldmatrix fragments (mapping verified in R13/R14 passing kernels).
// M=256 tile halves L2 tile traffic per MAC vs the R14 kernel (the binder).
// ---------------------------------------------------------------------------
__device__ __forceinline__ void gemm_body(
    const __nv_bfloat16* pAh, const __nv_bfloat16* pAl,
    const __nv_bfloat16* pBh, const __nv_bfloat16* pBl,
    int ldkA, int ldkB, int K,
    float* outp, int ldo, int y0, int n0)
{
    extern __shared__ __align__(16) uint8_t smem[];
    uint32_t sb = smem_u32(smem);

    const int tid  = threadIdx.x;
    const int lane = tid & 31;
    const int wid  = tid >> 5;             // 0..15
    const int grp  = lane >> 2;            // groupID (0..7)
    const int tig  = lane & 3;             // threadID_in_group (0..3)
    const int wm = wid & 3;                // 4 m-groups of 64 rows
    const int wn = wid >> 2;               // 4 n-groups of 32 cols

    // ldmatrix lane-address components (verified against PTX fragment tables):
    const int a_row = lane & 15;           // A: row within 16-row fragment
    const int a_k8  = lane >> 4;           // A: k8-half selector
    const int b_row = (lane & 7) + ((lane >> 4) << 3);   // B: n within 16-block
    const int b_k8  = (lane >> 3) & 1;     // B: k8-half selector

    float acc[4][4][4];                    // [m16 t][n8 q][elem]
#pragma unroll
    for (int t = 0; t < 4; t++)
#pragma unroll
        for (int q = 0; q < 4; q++)
#pragma unroll
            for (int e = 0; e < 4; e++) acc[t][q][e] = 0.f;

    const int NC = K >> 5;                 // K-chunk 32

    // prologue: chunk 0 -> stage 0
    {
        uint32_t st = sb;
        cp_tileA(st + OFF_AH, pAh, 0, ldkA, tid);
        cp_tileA(st + OFF_AL, pAl, 0, ldkA, tid);
        cp_tileB(st + OFF_BH, pBh, 0, ldkB, tid);
        cp_tileB(st + OFF_BL, pBl, 0, ldkB, tid);
        asm volatile("cp.async.commit_group;");
    }

    for (int c = 0; c < NC; c++) {
        if (c + 1 < NC) {
            uint32_t st = sb + (uint32_t)((c + 1) & 1) * STAGE_SB;
            int kb = (c + 1) * 32;
            cp_tileA(st + OFF_AH, pAh, kb, ldkA, tid);
            cp_tileA(st + OFF_AL, pAl, kb, ldkA, tid);
            cp_tileB(st + OFF_BH, pBh, kb, ldkB, tid);
            cp_tileB(st + OFF_BL, pBl, kb, ldkB, tid);
            asm volatile("cp.async.commit_group;");
            asm volatile("cp.async.wait_group 1;");   // chunk c complete
        } else {
            asm volatile("cp.async.wait_group 0;");
        }
        __syncthreads();                               // chunk c visible to all

        uint32_t st  = sb + (uint32_t)(c & 1) * STAGE_SB;
        const uint32_t sAh = st + OFF_AH;
        const uint32_t sAl = st + OFF_AL;
        const uint32_t sBh = st + OFF_BH;
        const uint32_t sBl = st + OFF_BL;

#pragma unroll
        for (int s = 0; s < 2; s++) {       // two k16 steps in the 32-chunk
            const uint32_t koffA = (uint32_t)((s * 16 + a_k8 * 8) * 2);
            const uint32_t koffB = (uint32_t)((s * 16 + b_k8 * 8) * 2);

            // --- B fragments for this warp's n32 (2 n16-blocks, hi/lo) ---
            uint32_t bhf[2][4], blf[2][4];
#pragma unroll
            for (int jj = 0; jj < 2; jj++) {
                uint32_t ob = (uint32_t)(wn * 32 + jj * 16 + b_row) * PITCH_B + koffB;
                ldsm4(sBh + ob, bhf[jj]);
                ldsm4(sBl + ob, blf[jj]);
            }
            // --- per m16 block: JIT A fragments, then 12 split MMAs ---
#pragma unroll
            for (int t = 0; t < 4; t++) {
                uint32_t oa = (uint32_t)(wm * 64 + t * 16 + a_row) * PITCH_B + koffA;
                uint32_t ahf[4], alf[4];
                ldsm4(sAh + oa, ahf);
                ldsm4(sAl + oa, alf);
#pragma unroll
                for (int jj = 0; jj < 2; jj++) {
                    mma16816(acc[t][2 * jj],     ahf, &bhf[jj][0]);
                    mma16816(acc[t][2 * jj],     ahf, &blf[jj][0]);
                    mma16816(acc[t][2 * jj],     alf, &bhf[jj][0]);
                    mma16816(acc[t][2 * jj + 1], ahf, &bhf[jj][2]);
                    mma16816(acc[t][2 * jj + 1], ahf, &blf[jj][2]);
                    mma16816(acc[t][2 * jj + 1], alf, &bhf[jj][2]);
                }
            }
        }
        __syncthreads();    // all warps done reading stage (c&1) before reuse
    }

    // Epilogue: direct stores. Quad (tig 0..3) covers 8 consecutive cols of one
    // row -> each 32B sector fully written. Guard m-rows >= Y_ (padding).
#pragma unroll
    for (int t = 0; t < 4; t++) {
        int r  = y0 + wm * 64 + t * 16 + grp;
#pragma unroll
        for (int q = 0; q < 4; q++) {
            int cc = n0 + wn * 32 + q * 8 + tig * 2;
            if (r < Y_) {
                outp[(size_t)r * ldo + cc]     = acc[t][q][0];
                outp[(size_t)r * ldo + cc + 1] = acc[t][q][1];
            }
            if (r + 8 < Y_) {
                outp[(size_t)(r + 8) * ldo + cc]     = acc[t][q][2];
                outp[(size_t)(r + 8) * ldo + cc + 1] = acc[t][q][3];
            }
        }
    }
}

// GEMM1 wrapper: scores[b,y,l] = U[y,:] . x[b,l,:]
// Device-global operands bound HERE (device code), not passed from host.
__global__ void __launch_bounds__(512, 1) gemm1_k(float* __restrict__ Sout)
{
    const int b  = blockIdx.z;
    const int y0 = blockIdx.y * 256;
    const int l0 = blockIdx.x * 128;
    gemm_body(g_U_hi + (size_t)y0 * D_,
              g_U_lo + (size_t)y0 * D_,
              g_x_hi + ((size_t)b * L_ + l0) * D_,
              g_x_lo + ((size_t)b * L_ + l0) * D_,
              D_, D_, D_,
              Sout + (size_t)b * Y_ * L_, L_, y0, l0);
}

// GEMM2 wrapper: m[b,y,d] = alpha[b,y,:] . xT[b,d,:]
__global__ void __launch_bounds__(512, 1) gemm2_k(float* __restrict__ Mout)
{
    const int b  = blockIdx.z;
    const int y0 = blockIdx.y * 256;
    const int n0 = blockIdx.x * 128;
    gemm_body(g_alpha_hi + ((size_t)b * YPAD_ + y0) * L_,
              g_alpha_lo + ((size_t)b * YPAD_ + y0) * L_,
              g_xT_hi + ((size_t)b * D_ + n0) * L_,
              g_xT_lo + ((size_t)b * D_ + n0) * L_,
              L_, L_, L_,
              Mout + (size_t)b * Y_ * D_, D_, y0, n0);
}

// ---------------------------------------------------------------------------
// Prep: split U (zero-padded to YPAD rows) and x (plus transposed xT).
// ---------------------------------------------------------------------------
__global__ __launch_bounds__(256) void split_U_kernel(const float* __restrict__ U)
{
    int idx = blockIdx.x * 256 + threadIdx.x;     // over YPAD_*D_
    int y = idx >> 9;
    float v = (y < Y_) ? U[idx] : 0.f;
    __nv_bfloat16 h = __float2bfloat16(v);
    g_U_hi[idx] = h;
    g_U_lo[idx] = __float2bfloat16(v - __bfloat162float(h));
}

__global__ __launch_bounds__(256) void split_x_kernel(const float* __restrict__ X)
{
    __shared__ float tile[32][33];
    int b = blockIdx.z, d0 = blockIdx.x * 32, l0 = blockIdx.y * 32;
    int tx = threadIdx.x, ty = threadIdx.y;       // (32, 8)
#pragma unroll
    for (int i = 0; i < 4; i++) {
        int l = l0 + ty + i * 8;
        size_t o = ((size_t)b * L_ + l) * D_ + d0 + tx;
        float v = X[o];
        tile[ty + i * 8][tx] = v;
        __nv_bfloat16 h = __float2bfloat16(v);
        g_x_hi[o] = h;
        g_x_lo[o] = __float2bfloat16(v - __bfloat162float(h));
    }
    __syncthreads();
#pragma unroll
    for (int i = 0; i < 4; i++) {
        int d = d0 + ty + i * 8;
        float v = tile[tx][ty + i * 8];
        size_t o = ((size_t)b * D_ + d) * L_ + l0 + tx;
        __nv_bfloat16 h = __float2bfloat16(v);
        g_xT_hi[o] = h;
        g_xT_lo[o] = __float2bfloat16(v - __bfloat162float(h));
    }
}

// ---------------------------------------------------------------------------
// Softmax over L=2048 rows, in place; also emits bf16 hi/lo split of alpha.
// ---------------------------------------------------------------------------
__global__ __launch_bounds__(256) void softmax_split(float* __restrict__ S)
{
    const int r = blockIdx.x;                     // 0..ROWS_-1
    const int b = r / Y_, y = r - b * Y_;
    float* p = S + (size_t)r * L_;
    __nv_bfloat16* ph = g_alpha_hi + ((size_t)b * YPAD_ + y) * L_;
    __nv_bfloat16* pl = g_alpha_lo + ((size_t)b * YPAD_ + y) * L_;
    const int t = threadIdx.x;

    float v[8];
    float mx = -3.402823466e38f;
#pragma unroll
    for (int j = 0; j < 8; j++) {
        v[j] = p[t + j * 256];
        mx = fmaxf(mx, v[j]);
    }
    __shared__ float sm[8];
#pragma unroll
    for (int o = 16; o; o >>= 1) mx = fmaxf(mx, __shfl_xor_sync(0xffffffffu, mx, o));
    if ((t & 31) == 0) sm[t >> 5] = mx;
    __syncthreads();
    mx = sm[0];
#pragma unroll
    for (int i = 1; i < 8; i++) mx = fmaxf(mx, sm[i]);
    __syncthreads();

    float sum = 0.f;
#pragma unroll
    for (int j = 0; j < 8; j++) { v[j] = expf(v[j] - mx); sum += v[j]; }
#pragma unroll
    for (int o = 16; o; o >>= 1) sum += __shfl_xor_sync(0xffffffffu, sum, o);
    if ((t & 31) == 0) sm[t >> 5] = sum;
    __syncthreads();
    sum = 0.f;
#pragma unroll
    for (int i = 0; i < 8; i++) sum += sm[i];
    float inv = 1.f / sum;

#pragma unroll
    for (int j = 0; j < 8; j++) {
        float o = v[j] * inv;
        int ix = t + j * 256;
        p[ix] = o;
        __nv_bfloat16 h = __float2bfloat16(o);
        ph[ix] = h;
        pl[ix] = __float2bfloat16(o - __bfloat162float(h));
    }
}

// ---------------------------------------------------------------------------
// Head + loss (unchanged).
// ---------------------------------------------------------------------------
__global__ __launch_bounds__(256) void head_kernel(
    const float* __restrict__ Mo, const float* __restrict__ FW,
    const float* __restrict__ bias, const float* __restrict__ target,
    float* __restrict__ Yout)
{
    const int w = threadIdx.x >> 5, lane = threadIdx.x & 31;
    const int g = blockIdx.x * 8 + w;
    const int yy = g % Y_;
    const float* mr = Mo + (size_t)g * D_;
    const float* fr = FW + (size_t)yy * D_;

    float s = 0.f;
#pragma unroll
    for (int j = 0; j < 16; j++)
        s = fmaf(mr[lane + j * 32], fr[lane + j * 32], s);
#pragma unroll
    for (int o = 16; o; o >>= 1) s += __shfl_xor_sync(0xffffffffu, s, o);

    __shared__ float sm[8];
    if (lane == 0) {
        float yv = s + bias[yy];
        Yout[g] = yv;
        float t = target[g];
        sm[w] = fmaxf(yv, 0.f) - yv * t + log1pf(expf(-fabsf(yv)));
    }
    __syncthreads();
    if (threadIdx.x == 0) {
        float acc = 0.f;
#pragma unroll
        for (int i = 0; i < 8; i++) acc += sm[i];
        g_partials[blockIdx.x] = acc;
    }
}

__global__ __launch_bounds__(1024) void loss_reduce(float* __restrict__ out)
{
    __shared__ double sm[32];
    double s = 0.0;
    for (int i = threadIdx.x; i < Y_; i += 1024) s += (double)g_partials[i];
#pragma unroll
    for (int o = 16; o; o >>= 1) s += __shfl_xor_sync(0xffffffffu, s, o);
    if ((threadIdx.x & 31) == 0) sm[threadIdx.x >> 5] = s;
    __syncthreads();
    if (threadIdx.x == 0) {
        double acc = 0.0;
#pragma unroll
        for (int i = 0; i < 32; i++) acc += sm[i];
        out[0] = (float)(acc / (double)ROWS_);
    }
}

// ---------------------------------------------------------------------------
// Launch. Inputs: x, target, text_inputs(unused), U_weight, final_weight,
// final_bias. Output tuple: (y, loss, alpha, m) flattened into d_out.
// Only harness-provided device pointers cross the host/device boundary.
// ---------------------------------------------------------------------------
extern "C" void kernel_launch(void* const* d_in, const int* in_sizes, int n_in,
                              void* d_out, int out_size)
{
    const float* x      = (const float*)d_in[0];
    const float* target = (const float*)d_in[1];
    const float* U      = (const float*)d_in[3];
    const float* FW     = (const float*)d_in[4];
    const float* bias   = (const float*)d_in[5];

    float* out       = (float*)d_out;
    float* out_y     = out;
    float* out_loss  = out + (size_t)ROWS_;
    float* out_alpha = out + (size_t)ROWS_ + 1;
    float* out_m     = out_alpha + (size_t)B_ * Y_ * L_;

    cudaFuncSetAttribute(gemm1_k, cudaFuncAttributeMaxDynamicSharedMemorySize, SMEM_GEMM);
    cudaFuncSetAttribute(gemm2_k, cudaFuncAttributeMaxDynamicSharedMemorySize, SMEM_GEMM);

    split_U_kernel<<<YPAD_ * D_ / 256, 256>>>(U);
    split_x_kernel<<<dim3(D_ / 32, L_ / 32, B_), dim3(32, 8)>>>(x);

    gemm1_k<<<dim3(L_ / 128, YPAD_ / 256, B_), 512, SMEM_GEMM>>>(out_alpha);

    softmax_split<<<ROWS_, 256>>>(out_alpha);

    gemm2_k<<<dim3(D_ / 128, YPAD_ / 256, B_), 512, SMEM_GEMM>>>(out_m);

    head_kernel<<<Y_, 256>>>(out_m, FW, bias, target, out_y);
    loss_reduce<<<1, 1024>>>(out_loss);
}

// round 16
// speedup vs baseline: 1.4982x; 1.4982x over previous
#include <cuda_runtime.h>
#include <cuda_fp16.h>
#include <math.h>
#include <stdint.h>

#define B_    8
#define L_    2048
#define D_    512
#define Y_    8921
#define YPAD_ 8960                 // 70 * 128
#define ROWS_ (B_ * Y_)            // 71368

#define A_SCALE   1024.0f          // keep A_lo out of fp16 subnormals
#define OUT_SCALE (1.0f / 1024.0f) // exact (power of 2)

// ---- static device scratch (no runtime allocation allowed) ----
__device__ float g_partials[Y_];
__device__ __align__(16) __half g_U_hi[YPAD_ * D_];        // U * 1024, hi
__device__ __align__(16) __half g_U_lo[YPAD_ * D_];        // U * 1024, lo
__device__ __align__(16) __half g_x_h[B_ * L_ * D_];       // x, single fp16 [b][l][d]
__device__ __align__(16) __half g_xT_h[B_ * D_ * L_];      // x^T, single fp16 [b][d][l]
__device__ __align__(16) __half g_alpha_hi[(size_t)B_ * YPAD_ * L_];  // alpha*1024 hi
__device__ __align__(16) __half g_alpha_lo[(size_t)B_ * YPAD_ * L_];  // alpha*1024 lo

// ---- helpers ----
__device__ __forceinline__ uint32_t smem_u32(const void* p) {
    uint32_t a;
    asm("{ .reg .u64 t; cvta.to.shared.u64 t, %1; cvt.u32.u64 %0, t; }" : "=r"(a) : "l"(p));
    return a;
}
__device__ __forceinline__ void ldsm4(uint32_t addr, uint32_t* r) {
    asm volatile("ldmatrix.sync.aligned.m8n8.x4.shared.b16 {%0,%1,%2,%3}, [%4];"
        : "=r"(r[0]), "=r"(r[1]), "=r"(r[2]), "=r"(r[3]) : "r"(addr));
}
__device__ __forceinline__ void mma16816(float* c, const uint32_t* a, const uint32_t* b) {
    asm volatile("mma.sync.aligned.m16n8k16.row.col.f32.f16.f16.f32 "
        "{%0,%1,%2,%3}, {%4,%5,%6,%7}, {%8,%9}, {%0,%1,%2,%3};"
        : "+f"(c[0]), "+f"(c[1]), "+f"(c[2]), "+f"(c[3])
        : "r"(a[0]), "r"(a[1]), "r"(a[2]), "r"(a[3]), "r"(b[0]), "r"(b[1]));
}

// SMEM tile geometry: 128 rows x 32 fp16 (64B data) with 80B pitch.
// 80 = 5*16: rows 16B-aligned (ldmatrix-legal); 8-row phases hit banks
// (20r mod 32) = full partition -> conflict-free ldmatrix by construction.
#define PITCH_B   80
#define TILE_SB   (128 * PITCH_B)     // 10240
#define STAGE_SB  (3 * TILE_SB)       // 30720 (A_hi, A_lo, B)
#define SMEM_GEMM (2 * STAGE_SB)      // 61440, double-buffered (2 CTAs/SM fit)
#define OFF_AH 0
#define OFF_AL TILE_SB
#define OFF_B  (2 * TILE_SB)

// cp.async one 128(rows) x 32(k fp16 = 64B) tile into padded-pitch SMEM.
__device__ __forceinline__ void cp_tile32(uint32_t dst, const __half* __restrict__ src,
                                          int kb, int ldk, int tid)
{
#pragma unroll
    for (int i = 0; i < 2; i++) {
        int seg = tid + i * 256;            // 0..511 segments of 16B
        int row = seg >> 2;                 // 4 segments per row
        int u   = seg & 3;
        const void* g = src + (size_t)row * ldk + kb + u * 8;
        uint32_t d = dst + (uint32_t)row * PITCH_B + (uint32_t)(u << 4);
        asm volatile("cp.async.ca.shared.global [%0], [%1], 16;" :: "r"(d), "l"(g));
    }
}

// ---------------------------------------------------------------------------
// HMMA GEMM body: C[m][n] = (1/1024) * sum_k A[m][k] * B[n][k], tile 128x128.
// A pre-split fp16 hi/lo (scaled x1024), B single fp16. fp32 accumulate,
// 2-product split: (ah + al) * b  -> error ~ a*(b - fp16(b)) ~ 2^-11.
// 8 warps (4m x 2n), K-chunk 32, cp.async 2-stage pipeline, ldmatrix frags
// (lane mapping carried unchanged from the verified R13/R14 kernels).
// ---------------------------------------------------------------------------
__device__ __forceinline__ void gemm_body(
    const __half* pAh, const __half* pAl, const __half* pB,
    int ldkA, int ldkB, int K,
    float* outp, int ldo, int y0, int n0)
{
    extern __shared__ __align__(16) uint8_t smem[];
    uint32_t sb = smem_u32(smem);

    const int tid  = threadIdx.x;
    const int lane = tid & 31;
    const int wid  = tid >> 5;
    const int grp  = lane >> 2;            // groupID (0..7)
    const int tig  = lane & 3;             // threadID_in_group (0..3)
    const int wm = wid & 3;                // 4 m-groups of 32 rows
    const int wn = wid >> 2;               // 2 n-groups of 64 cols

    // ldmatrix lane-address components (verified in passing R13/R14 kernels):
    const int a_row = lane & 15;           // A: row within 16-row fragment
    const int a_k8  = lane >> 4;           // A: k8-half selector
    const int b_row = (lane & 7) + ((lane >> 4) << 3);   // B: n within 16-block
    const int b_k8  = (lane >> 3) & 1;     // B: k8-half selector

    float acc[2][8][4];
#pragma unroll
    for (int t = 0; t < 2; t++)
#pragma unroll
        for (int q = 0; q < 8; q++)
#pragma unroll
            for (int e = 0; e < 4; e++) acc[t][q][e] = 0.f;

    const int NC = K >> 5;                 // K-chunk 32

    // prologue: chunk 0 -> stage 0
    {
        uint32_t st = sb;
        cp_tile32(st + OFF_AH, pAh, 0, ldkA, tid);
        cp_tile32(st + OFF_AL, pAl, 0, ldkA, tid);
        cp_tile32(st + OFF_B,  pB,  0, ldkB, tid);
        asm volatile("cp.async.commit_group;");
    }

    for (int c = 0; c < NC; c++) {
        if (c + 1 < NC) {
            uint32_t st = sb + (uint32_t)((c + 1) & 1) * STAGE_SB;
            int kb = (c + 1) * 32;
            cp_tile32(st + OFF_AH, pAh, kb, ldkA, tid);
            cp_tile32(st + OFF_AL, pAl, kb, ldkA, tid);
            cp_tile32(st + OFF_B,  pB,  kb, ldkB, tid);
            asm volatile("cp.async.commit_group;");
            asm volatile("cp.async.wait_group 1;");   // chunk c complete
        } else {
            asm volatile("cp.async.wait_group 0;");
        }
        __syncthreads();                               // chunk c visible to all

        uint32_t st  = sb + (uint32_t)(c & 1) * STAGE_SB;
        const uint32_t sAh = st + OFF_AH;
        const uint32_t sAl = st + OFF_AL;
        const uint32_t sB  = st + OFF_B;

#pragma unroll
        for (int s = 0; s < 2; s++) {       // two k16 steps in the 32-chunk
            const uint32_t koffA = (uint32_t)((s * 16 + a_k8 * 8) * 2);
            const uint32_t koffB = (uint32_t)((s * 16 + b_k8 * 8) * 2);

            // --- A fragments via ldmatrix.x4: hi & lo for both m16 blocks ---
            uint32_t ahf[2][4], alf[2][4];
#pragma unroll
            for (int t = 0; t < 2; t++) {
                uint32_t oa = (uint32_t)(wm * 32 + t * 16 + a_row) * PITCH_B + koffA;
                ldsm4(sAh + oa, ahf[t]);
                ldsm4(sAl + oa, alf[t]);
            }
            // --- B fragments per n16 block (single tile), then 2-product MMAs ---
#pragma unroll
            for (int jj = 0; jj < 4; jj++) {
                uint32_t ob = (uint32_t)(wn * 64 + jj * 16 + b_row) * PITCH_B + koffB;
                uint32_t bf[4];
                ldsm4(sB + ob, bf);
#pragma unroll
                for (int t = 0; t < 2; t++) {
                    mma16816(acc[t][2 * jj],     ahf[t], &bf[0]);
                    mma16816(acc[t][2 * jj],     alf[t], &bf[0]);
                    mma16816(acc[t][2 * jj + 1], ahf[t], &bf[2]);
                    mma16816(acc[t][2 * jj + 1], alf[t], &bf[2]);
                }
            }
        }
        __syncthreads();    // all warps done reading stage (c&1) before reuse
    }

    // Epilogue: unscale (exact pow2) + direct stores. Quad covers 8 adjacent
    // cols of one row -> full 32B sectors. Guard m-rows >= Y_ (padding).
#pragma unroll
    for (int t = 0; t < 2; t++) {
        int r  = y0 + wm * 32 + t * 16 + grp;
#pragma unroll
        for (int q = 0; q < 8; q++) {
            int cc = n0 + wn * 64 + q * 8 + tig * 2;
            if (r < Y_) {
                outp[(size_t)r * ldo + cc]     = acc[t][q][0] * OUT_SCALE;
                outp[(size_t)r * ldo + cc + 1] = acc[t][q][1] * OUT_SCALE;
            }
            if (r + 8 < Y_) {
                outp[(size_t)(r + 8) * ldo + cc]     = acc[t][q][2] * OUT_SCALE;
                outp[(size_t)(r + 8) * ldo + cc + 1] = acc[t][q][3] * OUT_SCALE;
            }
        }
    }
}

// GEMM1 wrapper: scores[b,y,l] = U[y,:] . x[b,l,:]
// Device-global operands bound HERE (device code), not passed from host.
__global__ void __launch_bounds__(256, 2) gemm1_k(float* __restrict__ Sout)
{
    const int b  = blockIdx.z;
    const int y0 = blockIdx.y * 128;
    const int l0 = blockIdx.x * 128;
    gemm_body(g_U_hi + (size_t)y0 * D_,
              g_U_lo + (size_t)y0 * D_,
              g_x_h + ((size_t)b * L_ + l0) * D_,
              D_, D_, D_,
              Sout + (size_t)b * Y_ * L_, L_, y0, l0);
}

// GEMM2 wrapper: m[b,y,d] = alpha[b,y,:] . xT[b,d,:]
__global__ void __launch_bounds__(256, 2) gemm2_k(float* __restrict__ Mout)
{
    const int b  = blockIdx.z;
    const int y0 = blockIdx.y * 128;
    const int n0 = blockIdx.x * 128;
    gemm_body(g_alpha_hi + ((size_t)b * YPAD_ + y0) * L_,
              g_alpha_lo + ((size_t)b * YPAD_ + y0) * L_,
              g_xT_h + ((size_t)b * D_ + n0) * L_,
              L_, L_, L_,
              Mout + (size_t)b * Y_ * D_, D_, y0, n0);
}

// ---------------------------------------------------------------------------
// Prep: split U*1024 (zero-padded to YPAD rows); x -> fp16 (plus transposed).
// ---------------------------------------------------------------------------
__global__ __launch_bounds__(256) void split_U_kernel(const float* __restrict__ U)
{
    int idx = blockIdx.x * 256 + threadIdx.x;     // over YPAD_*D_
    int y = idx >> 9;
    float v = (y < Y_) ? U[idx] * A_SCALE : 0.f;
    __half h = __float2half(v);
    g_U_hi[idx] = h;
    g_U_lo[idx] = __float2half(v - __half2float(h));
}

__global__ __launch_bounds__(256) void split_x_kernel(const float* __restrict__ X)
{
    __shared__ float tile[32][33];
    int b = blockIdx.z, d0 = blockIdx.x * 32, l0 = blockIdx.y * 32;
    int tx = threadIdx.x, ty = threadIdx.y;       // (32, 8)
#pragma unroll
    for (int i = 0; i < 4; i++) {
        int l = l0 + ty + i * 8;
        size_t o = ((size_t)b * L_ + l) * D_ + d0 + tx;
        float v = X[o];
        tile[ty + i * 8][tx] = v;
        g_x_h[o] = __float2half(v);
    }
    __syncthreads();
#pragma unroll
    for (int i = 0; i < 4; i++) {
        int d = d0 + ty + i * 8;
        float v = tile[tx][ty + i * 8];
        size_t o = ((size_t)b * D_ + d) * L_ + l0 + tx;
        g_xT_h[o] = __float2half(v);
    }
}

// ---------------------------------------------------------------------------
// Softmax over L=2048 rows, in place; emits fp16 hi/lo split of alpha*1024.
// ---------------------------------------------------------------------------
__global__ __launch_bounds__(256) void softmax_split(float* __restrict__ S)
{
    const int r = blockIdx.x;                     // 0..ROWS_-1
    const int b = r / Y_, y = r - b * Y_;
    float* p = S + (size_t)r * L_;
    __half* ph = g_alpha_hi + ((size_t)b * YPAD_ + y) * L_;
    __half* pl = g_alpha_lo + ((size_t)b * YPAD_ + y) * L_;
    const int t = threadIdx.x;

    float v[8];
    float mx = -3.402823466e38f;
#pragma unroll
    for (int j = 0; j < 8; j++) {
        v[j] = p[t + j * 256];
        mx = fmaxf(mx, v[j]);
    }
    __shared__ float sm[8];
#pragma unroll
    for (int o = 16; o; o >>= 1) mx = fmaxf(mx, __shfl_xor_sync(0xffffffffu, mx, o));
    if ((t & 31) == 0) sm[t >> 5] = mx;
    __syncthreads();
    mx = sm[0];
#pragma unroll
    for (int i = 1; i < 8; i++) mx = fmaxf(mx, sm[i]);
    __syncthreads();

    float sum = 0.f;
#pragma unroll
    for (int j = 0; j < 8; j++) { v[j] = expf(v[j] - mx); sum += v[j]; }
#pragma unroll
    for (int o = 16; o; o >>= 1) sum += __shfl_xor_sync(0xffffffffu, sum, o);
    if ((t & 31) == 0) sm[t >> 5] = sum;
    __syncthreads();
    sum = 0.f;
#pragma unroll
    for (int i = 0; i < 8; i++) sum += sm[i];
    float inv = 1.f / sum;

#pragma unroll
    for (int j = 0; j < 8; j++) {
        float o = v[j] * inv;
        int ix = t + j * 256;
        p[ix] = o;
        float os = o * A_SCALE;
        __half h = __float2half(os);
        ph[ix] = h;
        pl[ix] = __float2half(os - __half2float(h));
    }
}

// ---------------------------------------------------------------------------
// Head + loss (unchanged).
// ---------------------------------------------------------------------------
__global__ __launch_bounds__(256) void head_kernel(
    const float* __restrict__ Mo, const float* __restrict__ FW,
    const float* __restrict__ bias, const float* __restrict__ target,
    float* __restrict__ Yout)
{
    const int w = threadIdx.x >> 5, lane = threadIdx.x & 31;
    const int g = blockIdx.x * 8 + w;
    const int yy = g % Y_;
    const float* mr = Mo + (size_t)g * D_;
    const float* fr = FW + (size_t)yy * D_;

    float s = 0.f;
#pragma unroll
    for (int j = 0; j < 16; j++)
        s = fmaf(mr[lane + j * 32], fr[lane + j * 32], s);
#pragma unroll
    for (int o = 16; o; o >>= 1) s += __shfl_xor_sync(0xffffffffu, s, o);

    __shared__ float sm[8];
    if (lane == 0) {
        float yv = s + bias[yy];
        Yout[g] = yv;
        float t = target[g];
        sm[w] = fmaxf(yv, 0.f) - yv * t + log1pf(expf(-fabsf(yv)));
    }
    __syncthreads();
    if (threadIdx.x == 0) {
        float acc = 0.f;
#pragma unroll
        for (int i = 0; i < 8; i++) acc += sm[i];
        g_partials[blockIdx.x] = acc;
    }
}

__global__ __launch_bounds__(1024) void loss_reduce(float* __restrict__ out)
{
    __shared__ double sm[32];
    double s = 0.0;
    for (int i = threadIdx.x; i < Y_; i += 1024) s += (double)g_partials[i];
#pragma unroll
    for (int o = 16; o; o >>= 1) s += __shfl_xor_sync(0xffffffffu, s, o);
    if ((threadIdx.x & 31) == 0) sm[threadIdx.x >> 5] = s;
    __syncthreads();
    if (threadIdx.x == 0) {
        double acc = 0.0;
#pragma unroll
        for (int i = 0; i < 32; i++) acc += sm[i];
        out[0] = (float)(acc / (double)ROWS_);
    }
}

// ---------------------------------------------------------------------------
// Launch. Inputs: x, target, text_inputs(unused), U_weight, final_weight,
// final_bias. Output tuple: (y, loss, alpha, m) flattened into d_out.
// Only harness-provided device pointers cross the host/device boundary.
// ---------------------------------------------------------------------------
extern "C" void kernel_launch(void* const* d_in, const int* in_sizes, int n_in,
                              void* d_out, int out_size)
{
    const float* x      = (const float*)d_in[0];
    const float* target = (const float*)d_in[1];
    const float* U      = (const float*)d_in[3];
    const float* FW     = (const float*)d_in[4];
    const float* bias   = (const float*)d_in[5];

    float* out       = (float*)d_out;
    float* out_y     = out;
    float* out_loss  = out + (size_t)ROWS_;
    float* out_alpha = out + (size_t)ROWS_ + 1;
    float* out_m     = out_alpha + (size_t)B_ * Y_ * L_;

    cudaFuncSetAttribute(gemm1_k, cudaFuncAttributeMaxDynamicSharedMemorySize, SMEM_GEMM);
    cudaFuncSetAttribute(gemm2_k, cudaFuncAttributeMaxDynamicSharedMemorySize, SMEM_GEMM);

    split_U_kernel<<<YPAD_ * D_ / 256, 256>>>(U);
    split_x_kernel<<<dim3(D_ / 32, L_ / 32, B_), dim3(32, 8)>>>(x);

    gemm1_k<<<dim3(L_ / 128, YPAD_ / 128, B_), 256, SMEM_GEMM>>>(out_alpha);

    softmax_split<<<ROWS_, 256>>>(out_alpha);

    gemm2_k<<<dim3(D_ / 128, YPAD_ / 128, B_), 256, SMEM_GEMM>>>(out_m);

    head_kernel<<<Y_, 256>>>(out_m, FW, bias, target, out_y);
    loss_reduce<<<1, 1024>>>(out_loss);
}

// round 17
// speedup vs baseline: 1.7856x; 1.1919x over previous
#include <cuda_runtime.h>
#include <cuda_fp16.h>
#include <math.h>
#include <stdint.h>

#define B_    8
#define L_    2048
#define D_    512
#define Y_    8921
#define YPAD_ 8960                 // 70 * 128
#define ROWS_ (B_ * Y_)            // 71368

#define A_SCALE   1024.0f          // keep split-lo / small alphas in fp16 range
#define OUT_SCALE (1.0f / 1024.0f) // exact (power of 2)

// ---- static device scratch (no runtime allocation allowed) ----
__device__ float g_partials[Y_];
__device__ __align__(16) __half g_U_hi[YPAD_ * D_];        // U * 1024, hi
__device__ __align__(16) __half g_U_lo[YPAD_ * D_];        // U * 1024, lo
__device__ __align__(16) __half g_x_h[B_ * L_ * D_];       // x, single fp16 [b][l][d]
__device__ __align__(16) __half g_xT_h[B_ * D_ * L_];      // x^T, single fp16 [b][d][l]
__device__ __align__(16) __half g_alpha_h[(size_t)B_ * YPAD_ * L_];  // alpha*1024, single fp16

// ---- helpers ----
__device__ __forceinline__ uint32_t smem_u32(const void* p) {
    uint32_t a;
    asm("{ .reg .u64 t; cvta.to.shared.u64 t, %1; cvt.u32.u64 %0, t; }" : "=r"(a) : "l"(p));
    return a;
}
__device__ __forceinline__ void ldsm4(uint32_t addr, uint32_t* r) {
    asm volatile("ldmatrix.sync.aligned.m8n8.x4.shared.b16 {%0,%1,%2,%3}, [%4];"
        : "=r"(r[0]), "=r"(r[1]), "=r"(r[2]), "=r"(r[3]) : "r"(addr));
}
__device__ __forceinline__ void mma16816(float* c, const uint32_t* a, const uint32_t* b) {
    asm volatile("mma.sync.aligned.m16n8k16.row.col.f32.f16.f16.f32 "
        "{%0,%1,%2,%3}, {%4,%5,%6,%7}, {%8,%9}, {%0,%1,%2,%3};"
        : "+f"(c[0]), "+f"(c[1]), "+f"(c[2]), "+f"(c[3])
        : "r"(a[0]), "r"(a[1]), "r"(a[2]), "r"(a[3]), "r"(b[0]), "r"(b[1]));
}

// SMEM tile geometry: 128 rows x 32 fp16 (64B data) with 80B pitch.
// 80 = 5*16: rows 16B-aligned (ldmatrix-legal); 8-row phases hit banks
// (20r mod 32) = full partition -> conflict-free ldmatrix by construction.
#define PITCH_B   80
#define TILE_SB   (128 * PITCH_B)     // 10240
#define STAGE_SB  (3 * TILE_SB)       // 30720 (A_hi, A_lo?, B) - worst case
#define SMEM_GEMM (2 * STAGE_SB)      // 61440, double-buffered
#define OFF_AH 0
#define OFF_AL TILE_SB
#define OFF_B  (2 * TILE_SB)

// cp.async one 128(rows) x 32(k fp16 = 64B) tile into padded-pitch SMEM.
__device__ __forceinline__ void cp_tile32(uint32_t dst, const __half* __restrict__ src,
                                          int kb, int ldk, int tid)
{
#pragma unroll
    for (int i = 0; i < 2; i++) {
        int seg = tid + i * 256;            // 0..511 segments of 16B
        int row = seg >> 2;                 // 4 segments per row
        int u   = seg & 3;
        const void* g = src + (size_t)row * ldk + kb + u * 8;
        uint32_t d = dst + (uint32_t)row * PITCH_B + (uint32_t)(u << 4);
        asm volatile("cp.async.ca.shared.global [%0], [%1], 16;" :: "r"(d), "l"(g));
    }
}

// ---------------------------------------------------------------------------
// HMMA GEMM body: C[m][n] = (1/1024) * sum_k A[m][k] * B[n][k], tile 128x128.
// SPLIT_A=true : A pre-split fp16 hi/lo (scaled x1024) -> 2-product MMA.
// SPLIT_A=false: A single fp16 (scaled x1024)          -> 1-product MMA.
// B always single fp16. fp32 accumulate. 8 warps (4m x 2n), K-chunk 32,
// cp.async 2-stage pipeline, ldmatrix fragments (verified R13-R16 mapping).
// ---------------------------------------------------------------------------
template <bool SPLIT_A>
__device__ __forceinline__ void gemm_body(
    const __half* pAh, const __half* pAl, const __half* pB,
    int ldkA, int ldkB, int K,
    float* outp, int ldo, int y0, int n0)
{
    extern __shared__ __align__(16) uint8_t smem[];
    uint32_t sb = smem_u32(smem);

    const int tid  = threadIdx.x;
    const int lane = tid & 31;
    const int wid  = tid >> 5;
    const int grp  = lane >> 2;            // groupID (0..7)
    const int tig  = lane & 3;             // threadID_in_group (0..3)
    const int wm = wid & 3;                // 4 m-groups of 32 rows
    const int wn = wid >> 2;               // 2 n-groups of 64 cols

    // ldmatrix lane-address components (verified in passing R13-R16 kernels):
    const int a_row = lane & 15;           // A: row within 16-row fragment
    const int a_k8  = lane >> 4;           // A: k8-half selector
    const int b_row = (lane & 7) + ((lane >> 4) << 3);   // B: n within 16-block
    const int b_k8  = (lane >> 3) & 1;     // B: k8-half selector

    float acc[2][8][4];
#pragma unroll
    for (int t = 0; t < 2; t++)
#pragma unroll
        for (int q = 0; q < 8; q++)
#pragma unroll
            for (int e = 0; e < 4; e++) acc[t][q][e] = 0.f;

    const int NC = K >> 5;                 // K-chunk 32

    // prologue: chunk 0 -> stage 0
    {
        uint32_t st = sb;
        cp_tile32(st + OFF_AH, pAh, 0, ldkA, tid);
        if (SPLIT_A) cp_tile32(st + OFF_AL, pAl, 0, ldkA, tid);
        cp_tile32(st + OFF_B,  pB,  0, ldkB, tid);
        asm volatile("cp.async.commit_group;");
    }

    for (int c = 0; c < NC; c++) {
        if (c + 1 < NC) {
            uint32_t st = sb + (uint32_t)((c + 1) & 1) * STAGE_SB;
            int kb = (c + 1) * 32;
            cp_tile32(st + OFF_AH, pAh, kb, ldkA, tid);
            if (SPLIT_A) cp_tile32(st + OFF_AL, pAl, kb, ldkA, tid);
            cp_tile32(st + OFF_B,  pB,  kb, ldkB, tid);
            asm volatile("cp.async.commit_group;");
            asm volatile("cp.async.wait_group 1;");   // chunk c complete
        } else {
            asm volatile("cp.async.wait_group 0;");
        }
        __syncthreads();                               // chunk c visible to all

        uint32_t st  = sb + (uint32_t)(c & 1) * STAGE_SB;
        const uint32_t sAh = st + OFF_AH;
        const uint32_t sAl = st + OFF_AL;
        const uint32_t sB  = st + OFF_B;

#pragma unroll
        for (int s = 0; s < 2; s++) {       // two k16 steps in the 32-chunk
            const uint32_t koffA = (uint32_t)((s * 16 + a_k8 * 8) * 2);
            const uint32_t koffB = (uint32_t)((s * 16 + b_k8 * 8) * 2);

            // --- A fragments via ldmatrix.x4 ---
            uint32_t ahf[2][4], alf[2][4];
#pragma unroll
            for (int t = 0; t < 2; t++) {
                uint32_t oa = (uint32_t)(wm * 32 + t * 16 + a_row) * PITCH_B + koffA;
                ldsm4(sAh + oa, ahf[t]);
                if (SPLIT_A) ldsm4(sAl + oa, alf[t]);
            }
            // --- B fragments per n16 block, then 1- or 2-product MMAs ---
#pragma unroll
            for (int jj = 0; jj < 4; jj++) {
                uint32_t ob = (uint32_t)(wn * 64 + jj * 16 + b_row) * PITCH_B + koffB;
                uint32_t bf[4];
                ldsm4(sB + ob, bf);
#pragma unroll
                for (int t = 0; t < 2; t++) {
                    mma16816(acc[t][2 * jj],     ahf[t], &bf[0]);
                    mma16816(acc[t][2 * jj + 1], ahf[t], &bf[2]);
                    if (SPLIT_A) {
                        mma16816(acc[t][2 * jj],     alf[t], &bf[0]);
                        mma16816(acc[t][2 * jj + 1], alf[t], &bf[2]);
                    }
                }
            }
        }
        __syncthreads();    // all warps done reading stage (c&1) before reuse
    }

    // Epilogue: unscale (exact pow2) + direct stores. Quad covers 8 adjacent
    // cols of one row -> full 32B sectors. Guard m-rows >= Y_ (padding).
#pragma unroll
    for (int t = 0; t < 2; t++) {
        int r  = y0 + wm * 32 + t * 16 + grp;
#pragma unroll
        for (int q = 0; q < 8; q++) {
            int cc = n0 + wn * 64 + q * 8 + tig * 2;
            if (r < Y_) {
                outp[(size_t)r * ldo + cc]     = acc[t][q][0] * OUT_SCALE;
                outp[(size_t)r * ldo + cc + 1] = acc[t][q][1] * OUT_SCALE;
            }
            if (r + 8 < Y_) {
                outp[(size_t)(r + 8) * ldo + cc]     = acc[t][q][2] * OUT_SCALE;
                outp[(size_t)(r + 8) * ldo + cc + 1] = acc[t][q][3] * OUT_SCALE;
            }
        }
    }
}

// GEMM1 wrapper: scores[b,y,l] = U[y,:] . x[b,l,:]  (2-product: U split hi/lo)
// Device-global operands bound HERE (device code), not passed from host.
__global__ void __launch_bounds__(256, 2) gemm1_k(float* __restrict__ Sout)
{
    const int b  = blockIdx.z;
    const int y0 = blockIdx.y * 128;
    const int l0 = blockIdx.x * 128;
    gemm_body<true>(g_U_hi + (size_t)y0 * D_,
                    g_U_lo + (size_t)y0 * D_,
                    g_x_h + ((size_t)b * L_ + l0) * D_,
                    D_, D_, D_,
                    Sout + (size_t)b * Y_ * L_, L_, y0, l0);
}

// GEMM2 wrapper: m[b,y,d] = alpha[b,y,:] . xT[b,d,:]  (1-product: alpha single fp16)
__global__ void __launch_bounds__(256, 2) gemm2_k(float* __restrict__ Mout)
{
    const int b  = blockIdx.z;
    const int y0 = blockIdx.y * 128;
    const int n0 = blockIdx.x * 128;
    gemm_body<false>(g_alpha_h + ((size_t)b * YPAD_ + y0) * L_,
                     (const __half*)nullptr,
                     g_xT_h + ((size_t)b * D_ + n0) * L_,
                     L_, L_, L_,
                     Mout + (size_t)b * Y_ * D_, D_, y0, n0);
}

// ---------------------------------------------------------------------------
// Prep: split U*1024 (zero-padded to YPAD rows); x -> fp16 (plus transposed).
// ---------------------------------------------------------------------------
__global__ __launch_bounds__(256) void split_U_kernel(const float* __restrict__ U)
{
    int idx = blockIdx.x * 256 + threadIdx.x;     // over YPAD_*D_
    int y = idx >> 9;
    float v = (y < Y_) ? U[idx] * A_SCALE : 0.f;
    __half h = __float2half(v);
    g_U_hi[idx] = h;
    g_U_lo[idx] = __float2half(v - __half2float(h));
}

__global__ __launch_bounds__(256) void split_x_kernel(const float* __restrict__ X)
{
    __shared__ float tile[32][33];
    int b = blockIdx.z, d0 = blockIdx.x * 32, l0 = blockIdx.y * 32;
    int tx = threadIdx.x, ty = threadIdx.y;       // (32, 8)
#pragma unroll
    for (int i = 0; i < 4; i++) {
        int l = l0 + ty + i * 8;
        size_t o = ((size_t)b * L_ + l) * D_ + d0 + tx;
        float v = X[o];
        tile[ty + i * 8][tx] = v;
        g_x_h[o] = __float2half(v);
    }
    __syncthreads();
#pragma unroll
    for (int i = 0; i < 4; i++) {
        int d = d0 + ty + i * 8;
        float v = tile[tx][ty + i * 8];
        size_t o = ((size_t)b * D_ + d) * L_ + l0 + tx;
        g_xT_h[o] = __float2half(v);
    }
}

// ---------------------------------------------------------------------------
// Softmax over L=2048 rows, in place; emits single fp16 alpha*1024.
// ---------------------------------------------------------------------------
__global__ __launch_bounds__(256) void softmax_split(float* __restrict__ S)
{
    const int r = blockIdx.x;                     // 0..ROWS_-1
    const int b = r / Y_, y = r - b * Y_;
    float* p = S + (size_t)r * L_;
    __half* ph = g_alpha_h + ((size_t)b * YPAD_ + y) * L_;
    const int t = threadIdx.x;

    float v[8];
    float mx = -3.402823466e38f;
#pragma unroll
    for (int j = 0; j < 8; j++) {
        v[j] = p[t + j * 256];
        mx = fmaxf(mx, v[j]);
    }
    __shared__ float sm[8];
#pragma unroll
    for (int o = 16; o; o >>= 1) mx = fmaxf(mx, __shfl_xor_sync(0xffffffffu, mx, o));
    if ((t & 31) == 0) sm[t >> 5] = mx;
    __syncthreads();
    mx = sm[0];
#pragma unroll
    for (int i = 1; i < 8; i++) mx = fmaxf(mx, sm[i]);
    __syncthreads();

    float sum = 0.f;
#pragma unroll
    for (int j = 0; j < 8; j++) { v[j] = expf(v[j] - mx); sum += v[j]; }
#pragma unroll
    for (int o = 16; o; o >>= 1) sum += __shfl_xor_sync(0xffffffffu, sum, o);
    if ((t & 31) == 0) sm[t >> 5] = sum;
    __syncthreads();
    sum = 0.f;
#pragma unroll
    for (int i = 0; i < 8; i++) sum += sm[i];
    float inv = 1.f / sum;

#pragma unroll
    for (int j = 0; j < 8; j++) {
        float o = v[j] * inv;
        int ix = t + j * 256;
        p[ix] = o;
        ph[ix] = __float2half(o * A_SCALE);
    }
}

// ---------------------------------------------------------------------------
// Head + loss (unchanged).
// ---------------------------------------------------------------------------
__global__ __launch_bounds__(256) void head_kernel(
    const float* __restrict__ Mo, const float* __restrict__ FW,
    const float* __restrict__ bias, const float* __restrict__ target,
    float* __restrict__ Yout)
{
    const int w = threadIdx.x >> 5, lane = threadIdx.x & 31;
    const int g = blockIdx.x * 8 + w;
    const int yy = g % Y_;
    const float* mr = Mo + (size_t)g * D_;
    const float* fr = FW + (size_t)yy * D_;

    float s = 0.f;
#pragma unroll
    for (int j = 0; j < 16; j++)
        s = fmaf(mr[lane + j * 32], fr[lane + j * 32], s);
#pragma unroll
    for (int o = 16; o; o >>= 1) s += __shfl_xor_sync(0xffffffffu, s, o);

    __shared__ float sm[8];
    if (lane == 0) {
        float yv = s + bias[yy];
        Yout[g] = yv;
        float t = target[g];
        sm[w] = fmaxf(yv, 0.f) - yv * t + log1pf(expf(-fabsf(yv)));
    }
    __syncthreads();
    if (threadIdx.x == 0) {
        float acc = 0.f;
#pragma unroll
        for (int i = 0; i < 8; i++) acc += sm[i];
        g_partials[blockIdx.x] = acc;
    }
}

__global__ __launch_bounds__(1024) void loss_reduce(float* __restrict__ out)
{
    __shared__ double sm[32];
    double s = 0.0;
    for (int i = threadIdx.x; i < Y_; i += 1024) s += (double)g_partials[i];
#pragma unroll
    for (int o = 16; o; o >>= 1) s += __shfl_xor_sync(0xffffffffu, s, o);
    if ((threadIdx.x & 31) == 0) sm[threadIdx.x >> 5] = s;
    __syncthreads();
    if (threadIdx.x == 0) {
        double acc = 0.0;
#pragma unroll
        for (int i = 0; i < 32; i++) acc += sm[i];
        out[0] = (float)(acc / (double)ROWS_);
    }
}

// ---------------------------------------------------------------------------
// Launch. Inputs: x, target, text_inputs(unused), U_weight, final_weight,
// final_bias. Output tuple: (y, loss, alpha, m) flattened into d_out.
// Only harness-provided device pointers cross the host/device boundary.
// ---------------------------------------------------------------------------
extern "C" void kernel_launch(void* const* d_in, const int* in_sizes, int n_in,
                              void* d_out, int out_size)
{
    const float* x      = (const float*)d_in[0];
    const float* target = (const float*)d_in[1];
    const float* U      = (const float*)d_in[3];
    const float* FW     = (const float*)d_in[4];
    const float* bias   = (const float*)d_in[5];

    float* out       = (float*)d_out;
    float* out_y     = out;
    float* out_loss  = out + (size_t)ROWS_;
    float* out_alpha = out + (size_t)ROWS_ + 1;
    float* out_m     = out_alpha + (size_t)B_ * Y_ * L_;

    cudaFuncSetAttribute(gemm1_k, cudaFuncAttributeMaxDynamicSharedMemorySize, SMEM_GEMM);
    cudaFuncSetAttribute(gemm2_k, cudaFuncAttributeMaxDynamicSharedMemorySize, SMEM_GEMM);

    split_U_kernel<<<YPAD_ * D_ / 256, 256>>>(U);
    split_x_kernel<<<dim3(D_ / 32, L_ / 32, B_), dim3(32, 8)>>>(x);

    gemm1_k<<<dim3(L_ / 128, YPAD_ / 128, B_), 256, SMEM_GEMM>>>(out_alpha);

    softmax_split<<<ROWS_, 256>>>(out_alpha);

    gemm2_k<<<dim3(D_ / 128, YPAD_ / 128, B_), 256, SMEM_GEMM>>>(out_m);

    head_kernel<<<Y_, 256>>>(out_m, FW, bias, target, out_y);
    loss_reduce<<<1, 1024>>>(out_loss);
}